// round 6
// baseline (speedup 1.0000x reference)
#include <cuda_runtime.h>
#include <cuda_bf16.h>
#include <math.h>
#include <stdint.h>
#include <mma.h>

using namespace nvcuda;

// Problem constants
#define S_   256
#define B_   128
#define I_   1024
#define H_   512
#define G4  (4 * H_)            // 2048 gate columns
#define M_TOT (S_ * B_)         // 32768 rows of the input GEMM
#define NBLK 128

// ---------------------------------------------------------------------------
// Device scratch
// ---------------------------------------------------------------------------
__device__ float g_G[(size_t)M_TOT * G4];     // x@w_ih^T + bias  (268 MB)
__device__ float g_h[2][B_ * H_];             // double-buffered hidden state
__device__ int            g_cnt;              // grid barrier arrive counter
__device__ volatile int   g_gen;              // grid barrier generation
__device__ float g_bias_rep[16 * G4];         // bias replicated over 16 rows

// ---------------------------------------------------------------------------
// tf32 truncation (round-to-nearest-away), plain PTX, sm_80+ non-'a'
// ---------------------------------------------------------------------------
__device__ __forceinline__ float to_tf32(float x) {
    float r;
    asm("cvt.rna.tf32.f32 %0, %1;" : "=f"(r) : "f"(x));
    return r;
}

// ---------------------------------------------------------------------------
// Init: zero h0 and barrier state
// ---------------------------------------------------------------------------
__global__ void init_state() {
    int i = blockIdx.x * blockDim.x + threadIdx.x;
    if (i < B_ * H_) g_h[0][i] = 0.0f;
    if (i == 0) { g_cnt = 0; g_gen = 0; }
}

// ---------------------------------------------------------------------------
// Fill 16-row replicated bias strip (loaded as wmma C fragment)
// ---------------------------------------------------------------------------
__global__ void fill_bias(const float* __restrict__ bih,
                          const float* __restrict__ bhh) {
    int c = blockIdx.x * blockDim.x + threadIdx.x;
    if (c < G4) {
        float v = bih[c] + bhh[c];
#pragma unroll
        for (int r = 0; r < 16; r++) g_bias_rep[r * G4 + c] = v;
    }
}

// ---------------------------------------------------------------------------
// Phase 1: G = X @ W_ih^T + (b_ih + b_hh), split-tf32 x3 via WMMA m16n16k8.
// Split done IN-KERNEL from the original fp32 arrays (no staging buffers):
//   v = hi + lo, hi = tf32(v), lo = tf32(v - hi);  A@B ~= AhBh + AhBl + AlBh
// 128x128 block tile, BK=16 (two k=8 fragments), 8 warps (2 m x 4 n),
// each warp 64x32 via 4x2 tiles.
// ---------------------------------------------------------------------------
#define LDT 20   // smem row stride in floats (mult of 4, conflict-padded)

__global__ __launch_bounds__(256) void gemm_tf32(
    const float* __restrict__ X,
    const float* __restrict__ W)
{
    __shared__ float sAh[128 * LDT];
    __shared__ float sAl[128 * LDT];
    __shared__ float sBh[128 * LDT];
    __shared__ float sBl[128 * LDT];

    const int t   = threadIdx.x;
    const int wid = t >> 5;
    const int m0  = blockIdx.y * 128;
    const int n0  = blockIdx.x * 128;
    const int wr  = wid >> 2;     // 0..1 -> 64 M rows
    const int wc  = wid & 3;      // 0..3 -> 32 N cols

    // accumulators initialized from the replicated-bias strip (C fragment)
    wmma::fragment<wmma::accumulator, 16, 16, 8, float> acc[4][2];
#pragma unroll
    for (int mt = 0; mt < 4; mt++)
#pragma unroll
        for (int nt = 0; nt < 2; nt++)
            wmma::load_matrix_sync(acc[mt][nt],
                g_bias_rep + n0 + wc * 32 + nt * 16, G4, wmma::mem_row_major);

    // global staging: each thread owns (row = t>>1, 8-col half = (t&1)*8)
    const int lrow  = t >> 1;
    const int lhalf = (t & 1) * 8;
    const float* gA = X + (size_t)(m0 + lrow) * I_ + lhalf;
    const float* gB = W + (size_t)(n0 + lrow) * I_ + lhalf;

    for (int k0 = 0; k0 < I_; k0 += 16) {
        // load 8 fp32 of A-row and 8 of B-row, split to tf32 hi/lo in smem
        float4 a0 = *(const float4*)(gA + k0);
        float4 a1 = *(const float4*)(gA + k0 + 4);
        float4 b0 = *(const float4*)(gB + k0);
        float4 b1 = *(const float4*)(gB + k0 + 4);
        float av[8] = {a0.x, a0.y, a0.z, a0.w, a1.x, a1.y, a1.z, a1.w};
        float bv[8] = {b0.x, b0.y, b0.z, b0.w, b1.x, b1.y, b1.z, b1.w};
        __syncthreads();
#pragma unroll
        for (int i = 0; i < 8; i++) {
            float ah = to_tf32(av[i]);
            float bh = to_tf32(bv[i]);
            sAh[lrow * LDT + lhalf + i] = ah;
            sAl[lrow * LDT + lhalf + i] = to_tf32(av[i] - ah);
            sBh[lrow * LDT + lhalf + i] = bh;
            sBl[lrow * LDT + lhalf + i] = to_tf32(bv[i] - bh);
        }
        __syncthreads();

#pragma unroll
        for (int ks = 0; ks < 16; ks += 8) {
            wmma::fragment<wmma::matrix_a, 16, 16, 8, wmma::precision::tf32, wmma::row_major> ah[4], al[4];
            wmma::fragment<wmma::matrix_b, 16, 16, 8, wmma::precision::tf32, wmma::col_major> bh[2], bl[2];
#pragma unroll
            for (int mt = 0; mt < 4; mt++) {
                wmma::load_matrix_sync(ah[mt], &sAh[(wr * 64 + mt * 16) * LDT + ks], LDT);
                wmma::load_matrix_sync(al[mt], &sAl[(wr * 64 + mt * 16) * LDT + ks], LDT);
            }
#pragma unroll
            for (int nt = 0; nt < 2; nt++) {
                wmma::load_matrix_sync(bh[nt], &sBh[(wc * 32 + nt * 16) * LDT + ks], LDT);
                wmma::load_matrix_sync(bl[nt], &sBl[(wc * 32 + nt * 16) * LDT + ks], LDT);
            }
#pragma unroll
            for (int mt = 0; mt < 4; mt++)
#pragma unroll
                for (int nt = 0; nt < 2; nt++) {
                    wmma::mma_sync(acc[mt][nt], ah[mt], bh[nt], acc[mt][nt]);
                    wmma::mma_sync(acc[mt][nt], ah[mt], bl[nt], acc[mt][nt]);
                    wmma::mma_sync(acc[mt][nt], al[mt], bh[nt], acc[mt][nt]);
                }
        }
    }

    // epilogue: direct fragment store to g_G (bias already inside acc)
#pragma unroll
    for (int mt = 0; mt < 4; mt++)
#pragma unroll
        for (int nt = 0; nt < 2; nt++)
            wmma::store_matrix_sync(
                g_G + (size_t)(m0 + wr * 64 + mt * 16) * G4 + n0 + wc * 32 + nt * 16,
                acc[mt][nt], G4, wmma::mem_row_major);
}

// ---------------------------------------------------------------------------
// Phase 2: persistent LSTM recurrence (verified in round 2, unchanged).
// ---------------------------------------------------------------------------
#define SM_WT   0
#define SM_HS   32768
#define SM_GT   (32768 + 32 * 520)
#define SM_FLOATS (SM_GT + 64 * 33)

__global__ __launch_bounds__(256, 1) void lstm_persist(const float* __restrict__ Whh)
{
    extern __shared__ float sm[];
    float* w_t = sm + SM_WT;
    float* h_s = sm + SM_HS;
    float* gt  = sm + SM_GT;

    const int bid = blockIdx.x;
    const int cg  = bid >> 2;
    const int bg  = bid & 3;
    const int t   = threadIdx.x;
    const int jg  = t & 15;
    const int bgp = t >> 4;
    const int b0  = 2 * bgp;
    const int b1  = b0 + 1;

    {
        const int p  = t >> 2;
        const int kq = (t & 3) * 128;
        const int gj = (p >> 4) * H_ + cg * 16 + (p & 15);
        const float* wr = Whh + (size_t)gj * H_ + kq;
#pragma unroll 8
        for (int i = 0; i < 128; i += 4) {
            float4 v = *(const float4*)(wr + i);
            w_t[(kq + i + 0) * 64 + p] = v.x;
            w_t[(kq + i + 1) * 64 + p] = v.y;
            w_t[(kq + i + 2) * 64 + p] = v.z;
            w_t[(kq + i + 3) * 64 + p] = v.w;
        }
    }

    const int cc0 = 2 * t,     cc1 = 2 * t + 1;
    const int nn0 = cc0 >> 5,  bl0 = cc0 & 31;
    const int nn1 = cc1 >> 5,  bl1 = cc1 & 31;
    float creg0 = 0.0f, creg1 = 0.0f;

    const int gsel = jg >> 2;
    const int joff = gsel * H_ + cg * 16 + 4 * (jg & 3);

    __syncthreads();

    for (int s = 0; s < S_; ++s) {
        const float* Gs = g_G + (size_t)s * (B_ * G4);
        float4 ga = *(const float4*)(Gs + (size_t)(bg * 32 + b0) * G4 + joff);
        float4 gb = *(const float4*)(Gs + (size_t)(bg * 32 + b1) * G4 + joff);

        const float* h_in = g_h[s & 1];
        {
            const int row = t >> 3;
            const int kq2 = (t & 7) * 64;
            const float* src = h_in + (size_t)(bg * 32 + row) * H_ + kq2;
            float* dst = h_s + row * 520 + kq2;
#pragma unroll 4
            for (int i = 0; i < 64; i += 4)
                *(float4*)(dst + i) = *(const float4*)(src + i);
        }
        __syncthreads();

        float a00 = ga.x, a10 = ga.y, a20 = ga.z, a30 = ga.w;
        float a01 = gb.x, a11 = gb.y, a21 = gb.z, a31 = gb.w;

        const float* hr0 = h_s + b0 * 520;
        const float* hr1 = h_s + b1 * 520;
        const float* wp  = w_t + jg * 4;

#pragma unroll 2
        for (int k = 0; k < H_; k += 4) {
            float4 h0 = *(const float4*)(hr0 + k);
            float4 h1 = *(const float4*)(hr1 + k);
            float4 w;
            w = *(const float4*)(wp + (k + 0) * 64);
            a00 += w.x * h0.x; a10 += w.y * h0.x; a20 += w.z * h0.x; a30 += w.w * h0.x;
            a01 += w.x * h1.x; a11 += w.y * h1.x; a21 += w.z * h1.x; a31 += w.w * h1.x;
            w = *(const float4*)(wp + (k + 1) * 64);
            a00 += w.x * h0.y; a10 += w.y * h0.y; a20 += w.z * h0.y; a30 += w.w * h0.y;
            a01 += w.x * h1.y; a11 += w.y * h1.y; a21 += w.z * h1.y; a31 += w.w * h1.y;
            w = *(const float4*)(wp + (k + 2) * 64);
            a00 += w.x * h0.z; a10 += w.y * h0.z; a20 += w.z * h0.z; a30 += w.w * h0.z;
            a01 += w.x * h1.z; a11 += w.y * h1.z; a21 += w.z * h1.z; a31 += w.w * h1.z;
            w = *(const float4*)(wp + (k + 3) * 64);
            a00 += w.x * h0.w; a10 += w.y * h0.w; a20 += w.z * h0.w; a30 += w.w * h0.w;
            a01 += w.x * h1.w; a11 += w.y * h1.w; a21 += w.z * h1.w; a31 += w.w * h1.w;
        }

        gt[(4 * jg + 0) * 33 + b0] = a00;  gt[(4 * jg + 0) * 33 + b1] = a01;
        gt[(4 * jg + 1) * 33 + b0] = a10;  gt[(4 * jg + 1) * 33 + b1] = a11;
        gt[(4 * jg + 2) * 33 + b0] = a20;  gt[(4 * jg + 2) * 33 + b1] = a21;
        gt[(4 * jg + 3) * 33 + b0] = a30;  gt[(4 * jg + 3) * 33 + b1] = a31;
        __syncthreads();

        float* h_out = g_h[(s + 1) & 1];
        {
            float gi = gt[(0 * 16 + nn0) * 33 + bl0];
            float gf = gt[(1 * 16 + nn0) * 33 + bl0];
            float gg = gt[(2 * 16 + nn0) * 33 + bl0];
            float go = gt[(3 * 16 + nn0) * 33 + bl0];
            float si = 1.0f / (1.0f + __expf(-gi));
            float sf = 1.0f / (1.0f + __expf(-gf));
            float tg = tanhf(gg);
            float so = 1.0f / (1.0f + __expf(-go));
            creg0 = sf * creg0 + si * tg;
            h_out[(size_t)(bg * 32 + bl0) * H_ + cg * 16 + nn0] = so * tanhf(creg0);
        }
        {
            float gi = gt[(0 * 16 + nn1) * 33 + bl1];
            float gf = gt[(1 * 16 + nn1) * 33 + bl1];
            float gg = gt[(2 * 16 + nn1) * 33 + bl1];
            float go = gt[(3 * 16 + nn1) * 33 + bl1];
            float si = 1.0f / (1.0f + __expf(-gi));
            float sf = 1.0f / (1.0f + __expf(-gf));
            float tg = tanhf(gg);
            float so = 1.0f / (1.0f + __expf(-go));
            creg1 = sf * creg1 + si * tg;
            h_out[(size_t)(bg * 32 + bl1) * H_ + cg * 16 + nn1] = so * tanhf(creg1);
        }

        __threadfence();
        __syncthreads();
        if (t == 0) {
            int old = atomicAdd(&g_cnt, 1);
            if (old == NBLK - 1) {
                atomicExch(&g_cnt, 0);
                __threadfence();
                g_gen = s + 1;
            } else {
                while (g_gen <= s) { }
                __threadfence();
            }
        }
        __syncthreads();
    }
}

// ---------------------------------------------------------------------------
// Final reduction
// ---------------------------------------------------------------------------
__global__ __launch_bounds__(1024) void reduce_h(float* __restrict__ out) {
    __shared__ float red[1024];
    const int t = threadIdx.x;
    float s = 0.0f;
    for (int i = t; i < B_ * H_; i += 1024) s += g_h[0][i];
    red[t] = s;
    __syncthreads();
    for (int off = 512; off > 0; off >>= 1) {
        if (t < off) red[t] += red[t + off];
        __syncthreads();
    }
    if (t == 0) out[0] = red[0];
}

// ---------------------------------------------------------------------------
// kernel_launch
// ---------------------------------------------------------------------------
extern "C" void kernel_launch(void* const* d_in, const int* in_sizes, int n_in,
                              void* d_out, int out_size) {
    const float* x    = (const float*)d_in[0];
    const float* w_ih = (const float*)d_in[1];
    const float* w_hh = (const float*)d_in[2];
    const float* b_ih = (const float*)d_in[3];
    const float* b_hh = (const float*)d_in[4];
    float* out = (float*)d_out;

    static_assert(SM_FLOATS * 4 <= 227 * 1024, "smem overflow (lstm)");
    cudaFuncSetAttribute(lstm_persist,
                         cudaFuncAttributeMaxDynamicSharedMemorySize,
                         SM_FLOATS * sizeof(float));

    init_state<<<(B_ * H_ + 255) / 256, 256>>>();
    fill_bias<<<(G4 + 255) / 256, 256>>>(b_ih, b_hh);

    dim3 ggrid(G4 / 128, M_TOT / 128);   // (16 n-tiles, 256 m-tiles)
    gemm_tf32<<<ggrid, 256>>>(x, w_ih);

    lstm_persist<<<NBLK, 256, SM_FLOATS * sizeof(float)>>>(w_hh);

    reduce_h<<<1, 1024>>>(out);
}

// round 7
// speedup vs baseline: 1.6246x; 1.6246x over previous
#include <cuda_runtime.h>
#include <cuda_bf16.h>
#include <math.h>
#include <stdint.h>
#include <mma.h>

using namespace nvcuda;

// Problem constants
#define S_   256
#define B_   128
#define I_   1024
#define H_   512
#define G4  (4 * H_)            // 2048 gate columns
#define M_TOT (S_ * B_)         // 32768 rows of the input GEMM
#define NBLK 128

// ---------------------------------------------------------------------------
// Device scratch
// ---------------------------------------------------------------------------
__device__ float g_G[(size_t)M_TOT * G4];     // x@w_ih^T + bias  (268 MB)
__device__ float g_h[2][B_ * H_];             // double-buffered hidden state
__device__ int            g_cnt;              // grid barrier arrive counter
__device__ volatile int   g_gen;              // grid barrier generation
__device__ float g_bias_rep[16 * G4];         // bias replicated over 16 rows

// ---------------------------------------------------------------------------
// Init: zero h0 and barrier state
// ---------------------------------------------------------------------------
__global__ void init_state() {
    int i = blockIdx.x * blockDim.x + threadIdx.x;
    if (i < B_ * H_) g_h[0][i] = 0.0f;
    if (i == 0) { g_cnt = 0; g_gen = 0; }
}

// ---------------------------------------------------------------------------
// Fill 16-row replicated bias strip (loaded as wmma C fragment)
// ---------------------------------------------------------------------------
__global__ void fill_bias(const float* __restrict__ bih,
                          const float* __restrict__ bhh) {
    int c = blockIdx.x * blockDim.x + threadIdx.x;
    if (c < G4) {
        float v = bih[c] + bhh[c];
#pragma unroll
        for (int r = 0; r < 16; r++) g_bias_rep[r * G4 + c] = v;
    }
}

// ---------------------------------------------------------------------------
// Phase 1: G = X @ W_ih^T + (b_ih + b_hh), split-bf16 x3 via WMMA m16n16k16.
// Split done IN-KERNEL from the original fp32 arrays (no staging kernels,
// no bf16 global buffers):
//   v = hi + lo, hi = bf16(v), lo = bf16(v - hi);  A@B ~= AhBh + AhBl + AlBh
// 128x128 block tile, BK=16, 8 warps (2 m x 4 n), each warp 64x32 via 4x2
// m16n16k16 tiles; 3 mma_sync per tile.  Legacy bf16 HMMA = the fast
// non-tcgen05 tensor path on sm_103 (tf32 legacy is de-rated ~10x).
// ---------------------------------------------------------------------------
#define LDS_T 24   // smem row stride in bf16 (48B rows, conflict-padded)

__global__ __launch_bounds__(256) void gemm_bf16(
    const float* __restrict__ X,
    const float* __restrict__ W)
{
    __shared__ __nv_bfloat16 sAh[128 * LDS_T];
    __shared__ __nv_bfloat16 sAl[128 * LDS_T];
    __shared__ __nv_bfloat16 sBh[128 * LDS_T];
    __shared__ __nv_bfloat16 sBl[128 * LDS_T];

    const int t   = threadIdx.x;
    const int wid = t >> 5;
    const int m0  = blockIdx.y * 128;
    const int n0  = blockIdx.x * 128;
    const int wr  = wid >> 2;     // 0..1 -> 64 M rows
    const int wc  = wid & 3;      // 0..3 -> 32 N cols

    // accumulators initialized from the replicated-bias strip (C fragment)
    wmma::fragment<wmma::accumulator, 16, 16, 16, float> acc[4][2];
#pragma unroll
    for (int mt = 0; mt < 4; mt++)
#pragma unroll
        for (int nt = 0; nt < 2; nt++)
            wmma::load_matrix_sync(acc[mt][nt],
                g_bias_rep + n0 + wc * 32 + nt * 16, G4, wmma::mem_row_major);

    // global staging: each thread owns (row = t>>1, 8-col half = (t&1)*8)
    const int lrow  = t >> 1;
    const int lhalf = (t & 1) * 8;
    const float* gA = X + (size_t)(m0 + lrow) * I_ + lhalf;
    const float* gB = W + (size_t)(n0 + lrow) * I_ + lhalf;

    // register prefetch of the first chunk
    float4 a0 = *(const float4*)(gA);
    float4 a1 = *(const float4*)(gA + 4);
    float4 b0 = *(const float4*)(gB);
    float4 b1 = *(const float4*)(gB + 4);

    for (int k0 = 0; k0 < I_; k0 += 16) {
        // split fp32 -> (bf16 hi, bf16 lo), pack 8 bf16 = one uint4 store
        float av[8] = {a0.x, a0.y, a0.z, a0.w, a1.x, a1.y, a1.z, a1.w};
        float bv[8] = {b0.x, b0.y, b0.z, b0.w, b1.x, b1.y, b1.z, b1.w};
        uint32_t pah[4], pal[4], pbh[4], pbl[4];
#pragma unroll
        for (int i = 0; i < 4; i++) {
            float va0 = av[2 * i], va1 = av[2 * i + 1];
            float vb0 = bv[2 * i], vb1 = bv[2 * i + 1];
            __nv_bfloat162 h;
            h = __floats2bfloat162_rn(va0, va1);
            pah[i] = *(uint32_t*)&h;
            float la0 = va0 - __bfloat162float(h.x);
            float la1 = va1 - __bfloat162float(h.y);
            __nv_bfloat162 l = __floats2bfloat162_rn(la0, la1);
            pal[i] = *(uint32_t*)&l;
            h = __floats2bfloat162_rn(vb0, vb1);
            pbh[i] = *(uint32_t*)&h;
            float lb0 = vb0 - __bfloat162float(h.x);
            float lb1 = vb1 - __bfloat162float(h.y);
            l = __floats2bfloat162_rn(lb0, lb1);
            pbl[i] = *(uint32_t*)&l;
        }
        *(uint4*)&sAh[lrow * LDS_T + lhalf] = make_uint4(pah[0], pah[1], pah[2], pah[3]);
        *(uint4*)&sAl[lrow * LDS_T + lhalf] = make_uint4(pal[0], pal[1], pal[2], pal[3]);
        *(uint4*)&sBh[lrow * LDS_T + lhalf] = make_uint4(pbh[0], pbh[1], pbh[2], pbh[3]);
        *(uint4*)&sBl[lrow * LDS_T + lhalf] = make_uint4(pbl[0], pbl[1], pbl[2], pbl[3]);
        __syncthreads();

        // prefetch next chunk while tensor cores work
        if (k0 + 16 < I_) {
            a0 = *(const float4*)(gA + k0 + 16);
            a1 = *(const float4*)(gA + k0 + 20);
            b0 = *(const float4*)(gB + k0 + 16);
            b1 = *(const float4*)(gB + k0 + 20);
        }

        wmma::fragment<wmma::matrix_a, 16, 16, 16, __nv_bfloat16, wmma::row_major> ah[4], al[4];
        wmma::fragment<wmma::matrix_b, 16, 16, 16, __nv_bfloat16, wmma::col_major> bh[2], bl[2];
#pragma unroll
        for (int mt = 0; mt < 4; mt++) {
            wmma::load_matrix_sync(ah[mt], &sAh[(wr * 64 + mt * 16) * LDS_T], LDS_T);
            wmma::load_matrix_sync(al[mt], &sAl[(wr * 64 + mt * 16) * LDS_T], LDS_T);
        }
#pragma unroll
        for (int nt = 0; nt < 2; nt++) {
            wmma::load_matrix_sync(bh[nt], &sBh[(wc * 32 + nt * 16) * LDS_T], LDS_T);
            wmma::load_matrix_sync(bl[nt], &sBl[(wc * 32 + nt * 16) * LDS_T], LDS_T);
        }

#pragma unroll
        for (int mt = 0; mt < 4; mt++)
#pragma unroll
            for (int nt = 0; nt < 2; nt++) {
                wmma::mma_sync(acc[mt][nt], ah[mt], bh[nt], acc[mt][nt]);
                wmma::mma_sync(acc[mt][nt], ah[mt], bl[nt], acc[mt][nt]);
                wmma::mma_sync(acc[mt][nt], al[mt], bh[nt], acc[mt][nt]);
            }
        __syncthreads();
    }

    // epilogue: direct fragment store to g_G (bias already inside acc)
#pragma unroll
    for (int mt = 0; mt < 4; mt++)
#pragma unroll
        for (int nt = 0; nt < 2; nt++)
            wmma::store_matrix_sync(
                g_G + (size_t)(m0 + wr * 64 + mt * 16) * G4 + n0 + wc * 32 + nt * 16,
                acc[mt][nt], G4, wmma::mem_row_major);
}

// ---------------------------------------------------------------------------
// Phase 2: persistent LSTM recurrence (verified, unchanged).
// ---------------------------------------------------------------------------
#define SM_WT   0
#define SM_HS   32768
#define SM_GT   (32768 + 32 * 520)
#define SM_FLOATS (SM_GT + 64 * 33)

__global__ __launch_bounds__(256, 1) void lstm_persist(const float* __restrict__ Whh)
{
    extern __shared__ float sm[];
    float* w_t = sm + SM_WT;
    float* h_s = sm + SM_HS;
    float* gt  = sm + SM_GT;

    const int bid = blockIdx.x;
    const int cg  = bid >> 2;
    const int bg  = bid & 3;
    const int t   = threadIdx.x;
    const int jg  = t & 15;
    const int bgp = t >> 4;
    const int b0  = 2 * bgp;
    const int b1  = b0 + 1;

    {
        const int p  = t >> 2;
        const int kq = (t & 3) * 128;
        const int gj = (p >> 4) * H_ + cg * 16 + (p & 15);
        const float* wr = Whh + (size_t)gj * H_ + kq;
#pragma unroll 8
        for (int i = 0; i < 128; i += 4) {
            float4 v = *(const float4*)(wr + i);
            w_t[(kq + i + 0) * 64 + p] = v.x;
            w_t[(kq + i + 1) * 64 + p] = v.y;
            w_t[(kq + i + 2) * 64 + p] = v.z;
            w_t[(kq + i + 3) * 64 + p] = v.w;
        }
    }

    const int cc0 = 2 * t,     cc1 = 2 * t + 1;
    const int nn0 = cc0 >> 5,  bl0 = cc0 & 31;
    const int nn1 = cc1 >> 5,  bl1 = cc1 & 31;
    float creg0 = 0.0f, creg1 = 0.0f;

    const int gsel = jg >> 2;
    const int joff = gsel * H_ + cg * 16 + 4 * (jg & 3);

    __syncthreads();

    for (int s = 0; s < S_; ++s) {
        const float* Gs = g_G + (size_t)s * (B_ * G4);
        float4 ga = *(const float4*)(Gs + (size_t)(bg * 32 + b0) * G4 + joff);
        float4 gb = *(const float4*)(Gs + (size_t)(bg * 32 + b1) * G4 + joff);

        const float* h_in = g_h[s & 1];
        {
            const int row = t >> 3;
            const int kq2 = (t & 7) * 64;
            const float* src = h_in + (size_t)(bg * 32 + row) * H_ + kq2;
            float* dst = h_s + row * 520 + kq2;
#pragma unroll 4
            for (int i = 0; i < 64; i += 4)
                *(float4*)(dst + i) = *(const float4*)(src + i);
        }
        __syncthreads();

        float a00 = ga.x, a10 = ga.y, a20 = ga.z, a30 = ga.w;
        float a01 = gb.x, a11 = gb.y, a21 = gb.z, a31 = gb.w;

        const float* hr0 = h_s + b0 * 520;
        const float* hr1 = h_s + b1 * 520;
        const float* wp  = w_t + jg * 4;

#pragma unroll 2
        for (int k = 0; k < H_; k += 4) {
            float4 h0 = *(const float4*)(hr0 + k);
            float4 h1 = *(const float4*)(hr1 + k);
            float4 w;
            w = *(const float4*)(wp + (k + 0) * 64);
            a00 += w.x * h0.x; a10 += w.y * h0.x; a20 += w.z * h0.x; a30 += w.w * h0.x;
            a01 += w.x * h1.x; a11 += w.y * h1.x; a21 += w.z * h1.x; a31 += w.w * h1.x;
            w = *(const float4*)(wp + (k + 1) * 64);
            a00 += w.x * h0.y; a10 += w.y * h0.y; a20 += w.z * h0.y; a30 += w.w * h0.y;
            a01 += w.x * h1.y; a11 += w.y * h1.y; a21 += w.z * h1.y; a31 += w.w * h1.y;
            w = *(const float4*)(wp + (k + 2) * 64);
            a00 += w.x * h0.z; a10 += w.y * h0.z; a20 += w.z * h0.z; a30 += w.w * h0.z;
            a01 += w.x * h1.z; a11 += w.y * h1.z; a21 += w.z * h1.z; a31 += w.w * h1.z;
            w = *(const float4*)(wp + (k + 3) * 64);
            a00 += w.x * h0.w; a10 += w.y * h0.w; a20 += w.z * h0.w; a30 += w.w * h0.w;
            a01 += w.x * h1.w; a11 += w.y * h1.w; a21 += w.z * h1.w; a31 += w.w * h1.w;
        }

        gt[(4 * jg + 0) * 33 + b0] = a00;  gt[(4 * jg + 0) * 33 + b1] = a01;
        gt[(4 * jg + 1) * 33 + b0] = a10;  gt[(4 * jg + 1) * 33 + b1] = a11;
        gt[(4 * jg + 2) * 33 + b0] = a20;  gt[(4 * jg + 2) * 33 + b1] = a21;
        gt[(4 * jg + 3) * 33 + b0] = a30;  gt[(4 * jg + 3) * 33 + b1] = a31;
        __syncthreads();

        float* h_out = g_h[(s + 1) & 1];
        {
            float gi = gt[(0 * 16 + nn0) * 33 + bl0];
            float gf = gt[(1 * 16 + nn0) * 33 + bl0];
            float gg = gt[(2 * 16 + nn0) * 33 + bl0];
            float go = gt[(3 * 16 + nn0) * 33 + bl0];
            float si = 1.0f / (1.0f + __expf(-gi));
            float sf = 1.0f / (1.0f + __expf(-gf));
            float tg = tanhf(gg);
            float so = 1.0f / (1.0f + __expf(-go));
            creg0 = sf * creg0 + si * tg;
            h_out[(size_t)(bg * 32 + bl0) * H_ + cg * 16 + nn0] = so * tanhf(creg0);
        }
        {
            float gi = gt[(0 * 16 + nn1) * 33 + bl1];
            float gf = gt[(1 * 16 + nn1) * 33 + bl1];
            float gg = gt[(2 * 16 + nn1) * 33 + bl1];
            float go = gt[(3 * 16 + nn1) * 33 + bl1];
            float si = 1.0f / (1.0f + __expf(-gi));
            float sf = 1.0f / (1.0f + __expf(-gf));
            float tg = tanhf(gg);
            float so = 1.0f / (1.0f + __expf(-go));
            creg1 = sf * creg1 + si * tg;
            h_out[(size_t)(bg * 32 + bl1) * H_ + cg * 16 + nn1] = so * tanhf(creg1);
        }

        __threadfence();
        __syncthreads();
        if (t == 0) {
            int old = atomicAdd(&g_cnt, 1);
            if (old == NBLK - 1) {
                atomicExch(&g_cnt, 0);
                __threadfence();
                g_gen = s + 1;
            } else {
                while (g_gen <= s) { }
                __threadfence();
            }
        }
        __syncthreads();
    }
}

// ---------------------------------------------------------------------------
// Final reduction
// ---------------------------------------------------------------------------
__global__ __launch_bounds__(1024) void reduce_h(float* __restrict__ out) {
    __shared__ float red[1024];
    const int t = threadIdx.x;
    float s = 0.0f;
    for (int i = t; i < B_ * H_; i += 1024) s += g_h[0][i];
    red[t] = s;
    __syncthreads();
    for (int off = 512; off > 0; off >>= 1) {
        if (t < off) red[t] += red[t + off];
        __syncthreads();
    }
    if (t == 0) out[0] = red[0];
}

// ---------------------------------------------------------------------------
// kernel_launch
// ---------------------------------------------------------------------------
extern "C" void kernel_launch(void* const* d_in, const int* in_sizes, int n_in,
                              void* d_out, int out_size) {
    const float* x    = (const float*)d_in[0];
    const float* w_ih = (const float*)d_in[1];
    const float* w_hh = (const float*)d_in[2];
    const float* b_ih = (const float*)d_in[3];
    const float* b_hh = (const float*)d_in[4];
    float* out = (float*)d_out;

    static_assert(SM_FLOATS * 4 <= 227 * 1024, "smem overflow (lstm)");
    cudaFuncSetAttribute(lstm_persist,
                         cudaFuncAttributeMaxDynamicSharedMemorySize,
                         SM_FLOATS * sizeof(float));

    init_state<<<(B_ * H_ + 255) / 256, 256>>>();
    fill_bias<<<(G4 + 255) / 256, 256>>>(b_ih, b_hh);

    dim3 ggrid(G4 / 128, M_TOT / 128);   // (16 n-tiles, 256 m-tiles)
    gemm_bf16<<<ggrid, 256>>>(x, w_ih);

    lstm_persist<<<NBLK, 256, SM_FLOATS * sizeof(float)>>>(w_hh);

    reduce_h<<<1, 1024>>>(out);
}

// round 8
// speedup vs baseline: 2.1402x; 1.3174x over previous
#include <cuda_runtime.h>
#include <cuda_bf16.h>
#include <math.h>
#include <stdint.h>
#include <mma.h>

using namespace nvcuda;

// Problem constants
#define S_   256
#define B_   128
#define I_   1024
#define H_   512
#define G4  (4 * H_)            // 2048 gate columns
#define M_TOT (S_ * B_)         // 32768 rows of the input GEMM
#define NBLK 128

// ---------------------------------------------------------------------------
// Device scratch
// ---------------------------------------------------------------------------
__device__ float g_G[(size_t)M_TOT * G4];     // x@w_ih^T + bias  (268 MB)
__device__ float g_h[2][B_ * H_];             // double-buffered hidden state
__device__ int            g_cnt;              // grid barrier arrive counter
__device__ volatile int   g_gen;              // grid barrier generation
__device__ float g_bias_rep[16 * G4];         // bias replicated over 16 rows

// ---------------------------------------------------------------------------
// Init: zero h0 and barrier state
// ---------------------------------------------------------------------------
__global__ void init_state() {
    int i = blockIdx.x * blockDim.x + threadIdx.x;
    if (i < B_ * H_) g_h[0][i] = 0.0f;
    if (i == 0) { g_cnt = 0; g_gen = 0; }
}

// ---------------------------------------------------------------------------
// Fill 16-row replicated bias strip (loaded as wmma C fragment)
// ---------------------------------------------------------------------------
__global__ void fill_bias(const float* __restrict__ bih,
                          const float* __restrict__ bhh) {
    int c = blockIdx.x * blockDim.x + threadIdx.x;
    if (c < G4) {
        float v = bih[c] + bhh[c];
#pragma unroll
        for (int r = 0; r < 16; r++) g_bias_rep[r * G4 + c] = v;
    }
}

// ---------------------------------------------------------------------------
// Phase 1: G = X @ W_ih^T + bias, split-bf16 x3 WMMA (verified round 7).
// ---------------------------------------------------------------------------
#define LDS_T 24

__global__ __launch_bounds__(256) void gemm_bf16(
    const float* __restrict__ X,
    const float* __restrict__ W)
{
    __shared__ __nv_bfloat16 sAh[128 * LDS_T];
    __shared__ __nv_bfloat16 sAl[128 * LDS_T];
    __shared__ __nv_bfloat16 sBh[128 * LDS_T];
    __shared__ __nv_bfloat16 sBl[128 * LDS_T];

    const int t   = threadIdx.x;
    const int wid = t >> 5;
    const int m0  = blockIdx.y * 128;
    const int n0  = blockIdx.x * 128;
    const int wr  = wid >> 2;
    const int wc  = wid & 3;

    wmma::fragment<wmma::accumulator, 16, 16, 16, float> acc[4][2];
#pragma unroll
    for (int mt = 0; mt < 4; mt++)
#pragma unroll
        for (int nt = 0; nt < 2; nt++)
            wmma::load_matrix_sync(acc[mt][nt],
                g_bias_rep + n0 + wc * 32 + nt * 16, G4, wmma::mem_row_major);

    const int lrow  = t >> 1;
    const int lhalf = (t & 1) * 8;
    const float* gA = X + (size_t)(m0 + lrow) * I_ + lhalf;
    const float* gB = W + (size_t)(n0 + lrow) * I_ + lhalf;

    float4 a0 = *(const float4*)(gA);
    float4 a1 = *(const float4*)(gA + 4);
    float4 b0 = *(const float4*)(gB);
    float4 b1 = *(const float4*)(gB + 4);

    for (int k0 = 0; k0 < I_; k0 += 16) {
        float av[8] = {a0.x, a0.y, a0.z, a0.w, a1.x, a1.y, a1.z, a1.w};
        float bv[8] = {b0.x, b0.y, b0.z, b0.w, b1.x, b1.y, b1.z, b1.w};
        uint32_t pah[4], pal[4], pbh[4], pbl[4];
#pragma unroll
        for (int i = 0; i < 4; i++) {
            float va0 = av[2 * i], va1 = av[2 * i + 1];
            float vb0 = bv[2 * i], vb1 = bv[2 * i + 1];
            __nv_bfloat162 h;
            h = __floats2bfloat162_rn(va0, va1);
            pah[i] = *(uint32_t*)&h;
            __nv_bfloat162 l = __floats2bfloat162_rn(va0 - __bfloat162float(h.x),
                                                     va1 - __bfloat162float(h.y));
            pal[i] = *(uint32_t*)&l;
            h = __floats2bfloat162_rn(vb0, vb1);
            pbh[i] = *(uint32_t*)&h;
            l = __floats2bfloat162_rn(vb0 - __bfloat162float(h.x),
                                      vb1 - __bfloat162float(h.y));
            pbl[i] = *(uint32_t*)&l;
        }
        *(uint4*)&sAh[lrow * LDS_T + lhalf] = make_uint4(pah[0], pah[1], pah[2], pah[3]);
        *(uint4*)&sAl[lrow * LDS_T + lhalf] = make_uint4(pal[0], pal[1], pal[2], pal[3]);
        *(uint4*)&sBh[lrow * LDS_T + lhalf] = make_uint4(pbh[0], pbh[1], pbh[2], pbh[3]);
        *(uint4*)&sBl[lrow * LDS_T + lhalf] = make_uint4(pbl[0], pbl[1], pbl[2], pbl[3]);
        __syncthreads();

        if (k0 + 16 < I_) {
            a0 = *(const float4*)(gA + k0 + 16);
            a1 = *(const float4*)(gA + k0 + 20);
            b0 = *(const float4*)(gB + k0 + 16);
            b1 = *(const float4*)(gB + k0 + 20);
        }

        wmma::fragment<wmma::matrix_a, 16, 16, 16, __nv_bfloat16, wmma::row_major> ah[4], al[4];
        wmma::fragment<wmma::matrix_b, 16, 16, 16, __nv_bfloat16, wmma::col_major> bh[2], bl[2];
#pragma unroll
        for (int mt = 0; mt < 4; mt++) {
            wmma::load_matrix_sync(ah[mt], &sAh[(wr * 64 + mt * 16) * LDS_T], LDS_T);
            wmma::load_matrix_sync(al[mt], &sAl[(wr * 64 + mt * 16) * LDS_T], LDS_T);
        }
#pragma unroll
        for (int nt = 0; nt < 2; nt++) {
            wmma::load_matrix_sync(bh[nt], &sBh[(wc * 32 + nt * 16) * LDS_T], LDS_T);
            wmma::load_matrix_sync(bl[nt], &sBl[(wc * 32 + nt * 16) * LDS_T], LDS_T);
        }
#pragma unroll
        for (int mt = 0; mt < 4; mt++)
#pragma unroll
            for (int nt = 0; nt < 2; nt++) {
                wmma::mma_sync(acc[mt][nt], ah[mt], bh[nt], acc[mt][nt]);
                wmma::mma_sync(acc[mt][nt], ah[mt], bl[nt], acc[mt][nt]);
                wmma::mma_sync(acc[mt][nt], al[mt], bh[nt], acc[mt][nt]);
            }
        __syncthreads();
    }

#pragma unroll
    for (int mt = 0; mt < 4; mt++)
#pragma unroll
        for (int nt = 0; nt < 2; nt++)
            wmma::store_matrix_sync(
                g_G + (size_t)(m0 + wr * 64 + mt * 16) * G4 + n0 + wc * 32 + nt * 16,
                acc[mt][nt], G4, wmma::mem_row_major);
}

// ---------------------------------------------------------------------------
// Phase 2: persistent LSTM recurrence, recurrent GEMM on tensor cores.
// Block: cg = bid>>2 (16 hidden cols -> 64 gate rows), bg = bid&3 (32 batch).
// gates[64x32] = Whh_tile[64x512] @ h[32x512]^T via split-bf16 x3 WMMA,
// one 16x16 C tile per warp (8 warps = 4m x 2n), K = 32 k-tiles.
// w hi/lo staged to smem once; h hi/lo converted per step; gates exchanged
// via store_matrix_sync into smem; G added in the pointwise phase.
// ---------------------------------------------------------------------------
#define LDW 520                    // bf16 row stride for w tiles
#define LDH 520                    // bf16 row stride for h tiles
#define LDC 36                     // f32 row stride for gate exchange
#define OFF_WHI 0
#define OFF_WLO (OFF_WHI + 64 * LDW * 2)       // 66560
#define OFF_HHI (OFF_WLO + 64 * LDW * 2)       // 133120
#define OFF_HLO (OFF_HHI + 32 * LDH * 2)       // 166400
#define OFF_GT  (OFF_HLO + 32 * LDH * 2)       // 199680
#define LSTM_SMEM (OFF_GT + 64 * LDC * 4)      // 208896 bytes

__global__ __launch_bounds__(256, 1) void lstm_wmma(const float* __restrict__ Whh)
{
    extern __shared__ char sm[];
    __nv_bfloat16* w_hi = (__nv_bfloat16*)(sm + OFF_WHI);
    __nv_bfloat16* w_lo = (__nv_bfloat16*)(sm + OFF_WLO);
    __nv_bfloat16* h_hi = (__nv_bfloat16*)(sm + OFF_HHI);
    __nv_bfloat16* h_lo = (__nv_bfloat16*)(sm + OFF_HLO);
    float*         gt   = (float*)(sm + OFF_GT);

    const int bid = blockIdx.x;
    const int cg  = bid >> 2;      // 0..31
    const int bg  = bid & 3;       // 0..3
    const int t   = threadIdx.x;
    const int wid = t >> 5;        // 0..7
    const int mt  = wid >> 1;      // 0..3  -> gate rows [mt*16, mt*16+16)
    const int nt  = wid & 1;       // 0..1  -> batches   [nt*16, nt*16+16)

    // ---- stage W tile (64 x 512) as bf16 hi/lo, once ----
    {
        const int p   = t >> 2;              // 0..63 gate row
        const int ks  = (t & 3) * 128;       // k segment
        const int j   = (p >> 4) * H_ + cg * 16 + (p & 15);
        const float* src = Whh + (size_t)j * H_ + ks;
        __nv_bfloat16* dh = w_hi + p * LDW + ks;
        __nv_bfloat16* dl = w_lo + p * LDW + ks;
#pragma unroll 8
        for (int i = 0; i < 128; i += 4) {
            float4 v = *(const float4*)(src + i);
            __nv_bfloat162 h0 = __floats2bfloat162_rn(v.x, v.y);
            __nv_bfloat162 h1 = __floats2bfloat162_rn(v.z, v.w);
            __nv_bfloat162 l0 = __floats2bfloat162_rn(v.x - __bfloat162float(h0.x),
                                                      v.y - __bfloat162float(h0.y));
            __nv_bfloat162 l1 = __floats2bfloat162_rn(v.z - __bfloat162float(h1.x),
                                                      v.w - __bfloat162float(h1.y));
            *(uint32_t*)(dh + i)     = *(uint32_t*)&h0;
            *(uint32_t*)(dh + i + 2) = *(uint32_t*)&h1;
            *(uint32_t*)(dl + i)     = *(uint32_t*)&l0;
            *(uint32_t*)(dl + i + 2) = *(uint32_t*)&l1;
        }
    }

    // ---- pointwise cell mapping; c lives in registers ----
    const int cc0 = 2 * t,     cc1 = 2 * t + 1;
    const int nn0 = cc0 >> 5,  bl0 = cc0 & 31;     // hidden-col, batch
    const int nn1 = cc1 >> 5,  bl1 = cc1 & 31;
    float creg0 = 0.0f, creg1 = 0.0f;
    const size_t gb0 = (size_t)(bg * 32 + bl0) * G4 + cg * 16 + nn0;
    const size_t gb1 = (size_t)(bg * 32 + bl1) * G4 + cg * 16 + nn1;

    __syncthreads();

    for (int s = 0; s < S_; ++s) {
        // ---- prefetch this step's G gate values (hidden under MMA) ----
        const float* Gs = g_G + (size_t)s * (B_ * G4);
        float pg0[4], pg1[4];
#pragma unroll
        for (int g = 0; g < 4; g++) {
            pg0[g] = Gs[gb0 + g * H_];
            pg1[g] = Gs[gb1 + g * H_];
        }

        // ---- stage h tile (32 x 512) as bf16 hi/lo ----
        {
            const float* h_in = g_h[s & 1];
            const int row = t >> 3;            // 0..31
            const int ks  = (t & 7) * 64;
            const float* src = h_in + (size_t)(bg * 32 + row) * H_ + ks;
            __nv_bfloat16* dh = h_hi + row * LDH + ks;
            __nv_bfloat16* dl = h_lo + row * LDH + ks;
#pragma unroll 4
            for (int i = 0; i < 64; i += 4) {
                float4 v = *(const float4*)(src + i);
                __nv_bfloat162 h0 = __floats2bfloat162_rn(v.x, v.y);
                __nv_bfloat162 h1 = __floats2bfloat162_rn(v.z, v.w);
                __nv_bfloat162 l0 = __floats2bfloat162_rn(v.x - __bfloat162float(h0.x),
                                                          v.y - __bfloat162float(h0.y));
                __nv_bfloat162 l1 = __floats2bfloat162_rn(v.z - __bfloat162float(h1.x),
                                                          v.w - __bfloat162float(h1.y));
                *(uint32_t*)(dh + i)     = *(uint32_t*)&h0;
                *(uint32_t*)(dh + i + 2) = *(uint32_t*)&h1;
                *(uint32_t*)(dl + i)     = *(uint32_t*)&l0;
                *(uint32_t*)(dl + i + 2) = *(uint32_t*)&l1;
            }
        }
        __syncthreads();

        // ---- recurrent GEMM: each warp computes one 16x16 C tile ----
        {
            wmma::fragment<wmma::accumulator, 16, 16, 16, float> acc;
            wmma::fill_fragment(acc, 0.0f);
            const __nv_bfloat16* wbase_h = w_hi + (mt * 16) * LDW;
            const __nv_bfloat16* wbase_l = w_lo + (mt * 16) * LDW;
            const __nv_bfloat16* hbase_h = h_hi + (nt * 16) * LDH;
            const __nv_bfloat16* hbase_l = h_lo + (nt * 16) * LDH;
#pragma unroll 4
            for (int k = 0; k < 32; k++) {
                wmma::fragment<wmma::matrix_a, 16, 16, 16, __nv_bfloat16, wmma::row_major> a_h, a_l;
                wmma::fragment<wmma::matrix_b, 16, 16, 16, __nv_bfloat16, wmma::col_major> b_h, b_l;
                wmma::load_matrix_sync(a_h, wbase_h + k * 16, LDW);
                wmma::load_matrix_sync(a_l, wbase_l + k * 16, LDW);
                wmma::load_matrix_sync(b_h, hbase_h + k * 16, LDH);
                wmma::load_matrix_sync(b_l, hbase_l + k * 16, LDH);
                wmma::mma_sync(acc, a_h, b_h, acc);
                wmma::mma_sync(acc, a_h, b_l, acc);
                wmma::mma_sync(acc, a_l, b_h, acc);
            }
            wmma::store_matrix_sync(gt + (mt * 16) * LDC + nt * 16, acc, LDC,
                                    wmma::mem_row_major);
        }
        __syncthreads();

        // ---- pointwise LSTM update (2 cells per thread) ----
        float* h_out = g_h[(s + 1) & 1];
        {
            float gi = pg0[0] + gt[(0 * 16 + nn0) * LDC + bl0];
            float gf = pg0[1] + gt[(1 * 16 + nn0) * LDC + bl0];
            float gg = pg0[2] + gt[(2 * 16 + nn0) * LDC + bl0];
            float go = pg0[3] + gt[(3 * 16 + nn0) * LDC + bl0];
            float si = 1.0f / (1.0f + __expf(-gi));
            float sf = 1.0f / (1.0f + __expf(-gf));
            float tg = tanhf(gg);
            float so = 1.0f / (1.0f + __expf(-go));
            creg0 = sf * creg0 + si * tg;
            h_out[(size_t)(bg * 32 + bl0) * H_ + cg * 16 + nn0] = so * tanhf(creg0);
        }
        {
            float gi = pg1[0] + gt[(0 * 16 + nn1) * LDC + bl1];
            float gf = pg1[1] + gt[(1 * 16 + nn1) * LDC + bl1];
            float gg = pg1[2] + gt[(2 * 16 + nn1) * LDC + bl1];
            float go = pg1[3] + gt[(3 * 16 + nn1) * LDC + bl1];
            float si = 1.0f / (1.0f + __expf(-gi));
            float sf = 1.0f / (1.0f + __expf(-gf));
            float tg = tanhf(gg);
            float so = 1.0f / (1.0f + __expf(-go));
            creg1 = sf * creg1 + si * tg;
            h_out[(size_t)(bg * 32 + bl1) * H_ + cg * 16 + nn1] = so * tanhf(creg1);
        }

        // ---- grid barrier ----
        __threadfence();
        __syncthreads();
        if (t == 0) {
            int old = atomicAdd(&g_cnt, 1);
            if (old == NBLK - 1) {
                atomicExch(&g_cnt, 0);
                __threadfence();
                g_gen = s + 1;
            } else {
                while (g_gen <= s) { }
                __threadfence();
            }
        }
        __syncthreads();
    }
}

// ---------------------------------------------------------------------------
// Final reduction
// ---------------------------------------------------------------------------
__global__ __launch_bounds__(1024) void reduce_h(float* __restrict__ out) {
    __shared__ float red[1024];
    const int t = threadIdx.x;
    float s = 0.0f;
    for (int i = t; i < B_ * H_; i += 1024) s += g_h[0][i];
    red[t] = s;
    __syncthreads();
    for (int off = 512; off > 0; off >>= 1) {
        if (t < off) red[t] += red[t + off];
        __syncthreads();
    }
    if (t == 0) out[0] = red[0];
}

// ---------------------------------------------------------------------------
// kernel_launch
// ---------------------------------------------------------------------------
extern "C" void kernel_launch(void* const* d_in, const int* in_sizes, int n_in,
                              void* d_out, int out_size) {
    const float* x    = (const float*)d_in[0];
    const float* w_ih = (const float*)d_in[1];
    const float* w_hh = (const float*)d_in[2];
    const float* b_ih = (const float*)d_in[3];
    const float* b_hh = (const float*)d_in[4];
    float* out = (float*)d_out;

    static_assert(LSTM_SMEM <= 227 * 1024, "smem overflow (lstm)");
    cudaFuncSetAttribute(lstm_wmma,
                         cudaFuncAttributeMaxDynamicSharedMemorySize,
                         LSTM_SMEM);

    init_state<<<(B_ * H_ + 255) / 256, 256>>>();
    fill_bias<<<(G4 + 255) / 256, 256>>>(b_ih, b_hh);

    dim3 ggrid(G4 / 128, M_TOT / 128);
    gemm_bf16<<<ggrid, 256>>>(x, w_ih);

    lstm_wmma<<<NBLK, 256, LSTM_SMEM>>>(w_hh);

    reduce_h<<<1, 1024>>>(out);
}

// round 9
// speedup vs baseline: 2.2197x; 1.0372x over previous
#include <cuda_runtime.h>
#include <cuda_bf16.h>
#include <math.h>
#include <stdint.h>
#include <mma.h>

using namespace nvcuda;

// Problem constants
#define S_   256
#define B_   128
#define I_   1024
#define H_   512
#define G4  (4 * H_)            // 2048 gate columns
#define M_TOT (S_ * B_)         // 32768 rows of the input GEMM
#define NBLK 128

// ---------------------------------------------------------------------------
// Device scratch
// ---------------------------------------------------------------------------
__device__ float g_G[(size_t)M_TOT * G4];     // x@w_ih^T + bias  (268 MB)
__device__ float g_h[2][B_ * H_];             // double-buffered hidden state
__device__ int            g_cnt;              // grid barrier arrive counter
__device__ volatile int   g_gen;              // grid barrier generation
__device__ float g_bias_rep[16 * G4];         // bias replicated over 16 rows

// ---------------------------------------------------------------------------
// Init: zero h0 and barrier state
// ---------------------------------------------------------------------------
__global__ void init_state() {
    int i = blockIdx.x * blockDim.x + threadIdx.x;
    if (i < B_ * H_) g_h[0][i] = 0.0f;
    if (i == 0) { g_cnt = 0; g_gen = 0; }
}

// ---------------------------------------------------------------------------
// Fill 16-row replicated bias strip (loaded as wmma C fragment)
// ---------------------------------------------------------------------------
__global__ void fill_bias(const float* __restrict__ bih,
                          const float* __restrict__ bhh) {
    int c = blockIdx.x * blockDim.x + threadIdx.x;
    if (c < G4) {
        float v = bih[c] + bhh[c];
#pragma unroll
        for (int r = 0; r < 16; r++) g_bias_rep[r * G4 + c] = v;
    }
}

// ---------------------------------------------------------------------------
// split fp32x8 -> bf16 hi/lo, packed uint4 stores
// ---------------------------------------------------------------------------
__device__ __forceinline__ void split_store8(
    __nv_bfloat16* __restrict__ dh, __nv_bfloat16* __restrict__ dl,
    float4 v0, float4 v1)
{
    float av[8] = {v0.x, v0.y, v0.z, v0.w, v1.x, v1.y, v1.z, v1.w};
    uint32_t ph[4], pl[4];
#pragma unroll
    for (int i = 0; i < 4; i++) {
        float a = av[2 * i], b = av[2 * i + 1];
        __nv_bfloat162 h = __floats2bfloat162_rn(a, b);
        ph[i] = *(uint32_t*)&h;
        __nv_bfloat162 l = __floats2bfloat162_rn(a - __bfloat162float(h.x),
                                                 b - __bfloat162float(h.y));
        pl[i] = *(uint32_t*)&l;
    }
    *(uint4*)dh = make_uint4(ph[0], ph[1], ph[2], ph[3]);
    *(uint4*)dl = make_uint4(pl[0], pl[1], pl[2], pl[3]);
}

// ---------------------------------------------------------------------------
// Phase 1: G = X @ W_ih^T + bias, split-bf16 x3 WMMA, double-buffered smem,
// single __syncthreads per k-iteration, 2 CTAs/SM.
// ---------------------------------------------------------------------------
#define LDS_T 24
#define NIT   (I_ / 16)     // 64 k-iterations

__global__ __launch_bounds__(256, 2) void gemm_bf16(
    const float* __restrict__ X,
    const float* __restrict__ W)
{
    __shared__ __nv_bfloat16 sAh[2][128 * LDS_T];
    __shared__ __nv_bfloat16 sAl[2][128 * LDS_T];
    __shared__ __nv_bfloat16 sBh[2][128 * LDS_T];
    __shared__ __nv_bfloat16 sBl[2][128 * LDS_T];

    const int t   = threadIdx.x;
    const int wid = t >> 5;
    const int m0  = blockIdx.y * 128;
    const int n0  = blockIdx.x * 128;
    const int wr  = wid >> 2;
    const int wc  = wid & 3;

    wmma::fragment<wmma::accumulator, 16, 16, 16, float> acc[4][2];
#pragma unroll
    for (int mt = 0; mt < 4; mt++)
#pragma unroll
        for (int nt = 0; nt < 2; nt++)
            wmma::load_matrix_sync(acc[mt][nt],
                g_bias_rep + n0 + wc * 32 + nt * 16, G4, wmma::mem_row_major);

    const int lrow  = t >> 1;
    const int lhalf = (t & 1) * 8;
    const float* gA = X + (size_t)(m0 + lrow) * I_ + lhalf;
    const float* gB = W + (size_t)(n0 + lrow) * I_ + lhalf;
    const int soff = lrow * LDS_T + lhalf;

    // ---- prologue: stage chunk 0 into buffer 0, prefetch chunk 1 ----
    float4 a0 = *(const float4*)(gA);
    float4 a1 = *(const float4*)(gA + 4);
    float4 b0 = *(const float4*)(gB);
    float4 b1 = *(const float4*)(gB + 4);
    split_store8(&sAh[0][soff], &sAl[0][soff], a0, a1);
    split_store8(&sBh[0][soff], &sBl[0][soff], b0, b1);
    a0 = *(const float4*)(gA + 16);
    a1 = *(const float4*)(gA + 20);
    b0 = *(const float4*)(gB + 16);
    b1 = *(const float4*)(gB + 20);
    __syncthreads();

    for (int it = 0; it < NIT; ++it) {
        const int cur = it & 1;

        // stage chunk it+1 into the other buffer; prefetch chunk it+2.
        // Safe: end-of-(it-1) barrier guarantees all warps finished
        // reading buffer cur^1 (used in iteration it-1).
        if (it < NIT - 1) {
            split_store8(&sAh[cur ^ 1][soff], &sAl[cur ^ 1][soff], a0, a1);
            split_store8(&sBh[cur ^ 1][soff], &sBl[cur ^ 1][soff], b0, b1);
            if (it < NIT - 2) {
                const float* pa = gA + (it + 2) * 16;
                const float* pb = gB + (it + 2) * 16;
                a0 = *(const float4*)(pa);
                a1 = *(const float4*)(pa + 4);
                b0 = *(const float4*)(pb);
                b1 = *(const float4*)(pb + 4);
            }
        }

        // compute on buffer cur
        wmma::fragment<wmma::matrix_a, 16, 16, 16, __nv_bfloat16, wmma::row_major> ah[4], al[4];
        wmma::fragment<wmma::matrix_b, 16, 16, 16, __nv_bfloat16, wmma::col_major> bh[2], bl[2];
#pragma unroll
        for (int mt = 0; mt < 4; mt++) {
            wmma::load_matrix_sync(ah[mt], &sAh[cur][(wr * 64 + mt * 16) * LDS_T], LDS_T);
            wmma::load_matrix_sync(al[mt], &sAl[cur][(wr * 64 + mt * 16) * LDS_T], LDS_T);
        }
#pragma unroll
        for (int nt = 0; nt < 2; nt++) {
            wmma::load_matrix_sync(bh[nt], &sBh[cur][(wc * 32 + nt * 16) * LDS_T], LDS_T);
            wmma::load_matrix_sync(bl[nt], &sBl[cur][(wc * 32 + nt * 16) * LDS_T], LDS_T);
        }
#pragma unroll
        for (int mt = 0; mt < 4; mt++)
#pragma unroll
            for (int nt = 0; nt < 2; nt++) {
                wmma::mma_sync(acc[mt][nt], ah[mt], bh[nt], acc[mt][nt]);
                wmma::mma_sync(acc[mt][nt], ah[mt], bl[nt], acc[mt][nt]);
                wmma::mma_sync(acc[mt][nt], al[mt], bh[nt], acc[mt][nt]);
            }
        __syncthreads();
    }

#pragma unroll
    for (int mt = 0; mt < 4; mt++)
#pragma unroll
        for (int nt = 0; nt < 2; nt++)
            wmma::store_matrix_sync(
                g_G + (size_t)(m0 + wr * 64 + mt * 16) * G4 + n0 + wc * 32 + nt * 16,
                acc[mt][nt], G4, wmma::mem_row_major);
}

// ---------------------------------------------------------------------------
// Phase 2: persistent LSTM recurrence on tensor cores (verified round 8).
// ---------------------------------------------------------------------------
#define LDW 520
#define LDH 520
#define LDC 36
#define OFF_WHI 0
#define OFF_WLO (OFF_WHI + 64 * LDW * 2)
#define OFF_HHI (OFF_WLO + 64 * LDW * 2)
#define OFF_HLO (OFF_HHI + 32 * LDH * 2)
#define OFF_GT  (OFF_HLO + 32 * LDH * 2)
#define LSTM_SMEM (OFF_GT + 64 * LDC * 4)

__global__ __launch_bounds__(256, 1) void lstm_wmma(const float* __restrict__ Whh)
{
    extern __shared__ char sm[];
    __nv_bfloat16* w_hi = (__nv_bfloat16*)(sm + OFF_WHI);
    __nv_bfloat16* w_lo = (__nv_bfloat16*)(sm + OFF_WLO);
    __nv_bfloat16* h_hi = (__nv_bfloat16*)(sm + OFF_HHI);
    __nv_bfloat16* h_lo = (__nv_bfloat16*)(sm + OFF_HLO);
    float*         gt   = (float*)(sm + OFF_GT);

    const int bid = blockIdx.x;
    const int cg  = bid >> 2;
    const int bg  = bid & 3;
    const int t   = threadIdx.x;
    const int wid = t >> 5;
    const int mt  = wid >> 1;
    const int nt  = wid & 1;

    {
        const int p   = t >> 2;
        const int ks  = (t & 3) * 128;
        const int j   = (p >> 4) * H_ + cg * 16 + (p & 15);
        const float* src = Whh + (size_t)j * H_ + ks;
        __nv_bfloat16* dh = w_hi + p * LDW + ks;
        __nv_bfloat16* dl = w_lo + p * LDW + ks;
#pragma unroll 8
        for (int i = 0; i < 128; i += 4) {
            float4 v = *(const float4*)(src + i);
            __nv_bfloat162 h0 = __floats2bfloat162_rn(v.x, v.y);
            __nv_bfloat162 h1 = __floats2bfloat162_rn(v.z, v.w);
            __nv_bfloat162 l0 = __floats2bfloat162_rn(v.x - __bfloat162float(h0.x),
                                                      v.y - __bfloat162float(h0.y));
            __nv_bfloat162 l1 = __floats2bfloat162_rn(v.z - __bfloat162float(h1.x),
                                                      v.w - __bfloat162float(h1.y));
            *(uint32_t*)(dh + i)     = *(uint32_t*)&h0;
            *(uint32_t*)(dh + i + 2) = *(uint32_t*)&h1;
            *(uint32_t*)(dl + i)     = *(uint32_t*)&l0;
            *(uint32_t*)(dl + i + 2) = *(uint32_t*)&l1;
        }
    }

    const int cc0 = 2 * t,     cc1 = 2 * t + 1;
    const int nn0 = cc0 >> 5,  bl0 = cc0 & 31;
    const int nn1 = cc1 >> 5,  bl1 = cc1 & 31;
    float creg0 = 0.0f, creg1 = 0.0f;
    const size_t gb0 = (size_t)(bg * 32 + bl0) * G4 + cg * 16 + nn0;
    const size_t gb1 = (size_t)(bg * 32 + bl1) * G4 + cg * 16 + nn1;

    __syncthreads();

    for (int s = 0; s < S_; ++s) {
        const float* Gs = g_G + (size_t)s * (B_ * G4);
        float pg0[4], pg1[4];
#pragma unroll
        for (int g = 0; g < 4; g++) {
            pg0[g] = Gs[gb0 + g * H_];
            pg1[g] = Gs[gb1 + g * H_];
        }

        {
            const float* h_in = g_h[s & 1];
            const int row = t >> 3;
            const int ks  = (t & 7) * 64;
            const float* src = h_in + (size_t)(bg * 32 + row) * H_ + ks;
            __nv_bfloat16* dh = h_hi + row * LDH + ks;
            __nv_bfloat16* dl = h_lo + row * LDH + ks;
#pragma unroll 4
            for (int i = 0; i < 64; i += 4) {
                float4 v = *(const float4*)(src + i);
                __nv_bfloat162 h0 = __floats2bfloat162_rn(v.x, v.y);
                __nv_bfloat162 h1 = __floats2bfloat162_rn(v.z, v.w);
                __nv_bfloat162 l0 = __floats2bfloat162_rn(v.x - __bfloat162float(h0.x),
                                                          v.y - __bfloat162float(h0.y));
                __nv_bfloat162 l1 = __floats2bfloat162_rn(v.z - __bfloat162float(h1.x),
                                                          v.w - __bfloat162float(h1.y));
                *(uint32_t*)(dh + i)     = *(uint32_t*)&h0;
                *(uint32_t*)(dh + i + 2) = *(uint32_t*)&h1;
                *(uint32_t*)(dl + i)     = *(uint32_t*)&l0;
                *(uint32_t*)(dl + i + 2) = *(uint32_t*)&l1;
            }
        }
        __syncthreads();

        {
            wmma::fragment<wmma::accumulator, 16, 16, 16, float> acc;
            wmma::fill_fragment(acc, 0.0f);
            const __nv_bfloat16* wbase_h = w_hi + (mt * 16) * LDW;
            const __nv_bfloat16* wbase_l = w_lo + (mt * 16) * LDW;
            const __nv_bfloat16* hbase_h = h_hi + (nt * 16) * LDH;
            const __nv_bfloat16* hbase_l = h_lo + (nt * 16) * LDH;
#pragma unroll 4
            for (int k = 0; k < 32; k++) {
                wmma::fragment<wmma::matrix_a, 16, 16, 16, __nv_bfloat16, wmma::row_major> a_h, a_l;
                wmma::fragment<wmma::matrix_b, 16, 16, 16, __nv_bfloat16, wmma::col_major> b_h, b_l;
                wmma::load_matrix_sync(a_h, wbase_h + k * 16, LDW);
                wmma::load_matrix_sync(a_l, wbase_l + k * 16, LDW);
                wmma::load_matrix_sync(b_h, hbase_h + k * 16, LDH);
                wmma::load_matrix_sync(b_l, hbase_l + k * 16, LDH);
                wmma::mma_sync(acc, a_h, b_h, acc);
                wmma::mma_sync(acc, a_h, b_l, acc);
                wmma::mma_sync(acc, a_l, b_h, acc);
            }
            wmma::store_matrix_sync(gt + (mt * 16) * LDC + nt * 16, acc, LDC,
                                    wmma::mem_row_major);
        }
        __syncthreads();

        float* h_out = g_h[(s + 1) & 1];
        {
            float gi = pg0[0] + gt[(0 * 16 + nn0) * LDC + bl0];
            float gf = pg0[1] + gt[(1 * 16 + nn0) * LDC + bl0];
            float gg = pg0[2] + gt[(2 * 16 + nn0) * LDC + bl0];
            float go = pg0[3] + gt[(3 * 16 + nn0) * LDC + bl0];
            float si = 1.0f / (1.0f + __expf(-gi));
            float sf = 1.0f / (1.0f + __expf(-gf));
            float tg = tanhf(gg);
            float so = 1.0f / (1.0f + __expf(-go));
            creg0 = sf * creg0 + si * tg;
            h_out[(size_t)(bg * 32 + bl0) * H_ + cg * 16 + nn0] = so * tanhf(creg0);
        }
        {
            float gi = pg1[0] + gt[(0 * 16 + nn1) * LDC + bl1];
            float gf = pg1[1] + gt[(1 * 16 + nn1) * LDC + bl1];
            float gg = pg1[2] + gt[(2 * 16 + nn1) * LDC + bl1];
            float go = pg1[3] + gt[(3 * 16 + nn1) * LDC + bl1];
            float si = 1.0f / (1.0f + __expf(-gi));
            float sf = 1.0f / (1.0f + __expf(-gf));
            float tg = tanhf(gg);
            float so = 1.0f / (1.0f + __expf(-go));
            creg1 = sf * creg1 + si * tg;
            h_out[(size_t)(bg * 32 + bl1) * H_ + cg * 16 + nn1] = so * tanhf(creg1);
        }

        __threadfence();
        __syncthreads();
        if (t == 0) {
            int old = atomicAdd(&g_cnt, 1);
            if (old == NBLK - 1) {
                atomicExch(&g_cnt, 0);
                __threadfence();
                g_gen = s + 1;
            } else {
                while (g_gen <= s) { }
                __threadfence();
            }
        }
        __syncthreads();
    }
}

// ---------------------------------------------------------------------------
// Final reduction
// ---------------------------------------------------------------------------
__global__ __launch_bounds__(1024) void reduce_h(float* __restrict__ out) {
    __shared__ float red[1024];
    const int t = threadIdx.x;
    float s = 0.0f;
    for (int i = t; i < B_ * H_; i += 1024) s += g_h[0][i];
    red[t] = s;
    __syncthreads();
    for (int off = 512; off > 0; off >>= 1) {
        if (t < off) red[t] += red[t + off];
        __syncthreads();
    }
    if (t == 0) out[0] = red[0];
}

// ---------------------------------------------------------------------------
// kernel_launch
// ---------------------------------------------------------------------------
extern "C" void kernel_launch(void* const* d_in, const int* in_sizes, int n_in,
                              void* d_out, int out_size) {
    const float* x    = (const float*)d_in[0];
    const float* w_ih = (const float*)d_in[1];
    const float* w_hh = (const float*)d_in[2];
    const float* b_ih = (const float*)d_in[3];
    const float* b_hh = (const float*)d_in[4];
    float* out = (float*)d_out;

    static_assert(LSTM_SMEM <= 227 * 1024, "smem overflow (lstm)");
    cudaFuncSetAttribute(lstm_wmma,
                         cudaFuncAttributeMaxDynamicSharedMemorySize,
                         LSTM_SMEM);

    init_state<<<(B_ * H_ + 255) / 256, 256>>>();
    fill_bias<<<(G4 + 255) / 256, 256>>>(b_ih, b_hh);

    dim3 ggrid(G4 / 128, M_TOT / 128);
    gemm_bf16<<<ggrid, 256>>>(x, w_ih);

    lstm_wmma<<<NBLK, 256, LSTM_SMEM>>>(w_hh);

    reduce_h<<<1, 1024>>>(out);
}

// round 10
// speedup vs baseline: 2.6041x; 1.1732x over previous
#include <cuda_runtime.h>
#include <cuda_bf16.h>
#include <cuda_fp16.h>
#include <math.h>
#include <stdint.h>
#include <mma.h>

using namespace nvcuda;

// Problem constants
#define S_   256
#define B_   128
#define I_   1024
#define H_   512
#define G4  (4 * H_)            // 2048 gate columns
#define M_TOT (S_ * B_)         // 32768 rows of the input GEMM
#define NBLK 128

// ---------------------------------------------------------------------------
// Device scratch
// ---------------------------------------------------------------------------
__device__ float g_G[(size_t)M_TOT * G4];     // x@w_ih^T + bias  (268 MB)
__device__ float g_h[2][B_ * H_];             // double-buffered hidden state
__device__ int            g_cnt;              // grid barrier arrive counter
__device__ volatile int   g_gen;              // grid barrier generation
__device__ float g_bias_rep[16 * G4];         // bias replicated over 16 rows

// ---------------------------------------------------------------------------
// Init: zero h0 and barrier state
// ---------------------------------------------------------------------------
__global__ void init_state() {
    int i = blockIdx.x * blockDim.x + threadIdx.x;
    if (i < B_ * H_) g_h[0][i] = 0.0f;
    if (i == 0) { g_cnt = 0; g_gen = 0; }
}

// ---------------------------------------------------------------------------
// Fill 16-row replicated bias strip (loaded as wmma C fragment)
// ---------------------------------------------------------------------------
__global__ void fill_bias(const float* __restrict__ bih,
                          const float* __restrict__ bhh) {
    int c = blockIdx.x * blockDim.x + threadIdx.x;
    if (c < G4) {
        float v = bih[c] + bhh[c];
#pragma unroll
        for (int r = 0; r < 16; r++) g_bias_rep[r * G4 + c] = v;
    }
}

// ---------------------------------------------------------------------------
// pack fp32x8 -> fp16x8, one uint4 store
// ---------------------------------------------------------------------------
__device__ __forceinline__ void half_store8(
    __half* __restrict__ dst, float4 v0, float4 v1)
{
    __half2 h0 = __floats2half2_rn(v0.x, v0.y);
    __half2 h1 = __floats2half2_rn(v0.z, v0.w);
    __half2 h2 = __floats2half2_rn(v1.x, v1.y);
    __half2 h3 = __floats2half2_rn(v1.z, v1.w);
    *(uint4*)dst = make_uint4(*(uint32_t*)&h0, *(uint32_t*)&h1,
                              *(uint32_t*)&h2, *(uint32_t*)&h3);
}

// ---------------------------------------------------------------------------
// Phase 1: G = X @ W_ih^T + bias, single-term fp16 WMMA, double-buffered.
// Gate abs error ~6e-4 -> output rel ~6e-5 (calibrated factor 0.09).
// 128x128 block tile, BK=16, 8 warps (2m x 4n), 4x2 m16n16k16 tiles/warp,
// 8 mma_sync per warp-iter (was 24 with split-bf16 x3).
// ---------------------------------------------------------------------------
#define LDS_T 24
#define NIT   (I_ / 16)     // 64 k-iterations

__global__ __launch_bounds__(256, 2) void gemm_fp16(
    const float* __restrict__ X,
    const float* __restrict__ W)
{
    __shared__ __half sA[2][128 * LDS_T];
    __shared__ __half sB[2][128 * LDS_T];

    const int t   = threadIdx.x;
    const int wid = t >> 5;
    const int m0  = blockIdx.y * 128;
    const int n0  = blockIdx.x * 128;
    const int wr  = wid >> 2;
    const int wc  = wid & 3;

    wmma::fragment<wmma::accumulator, 16, 16, 16, float> acc[4][2];
#pragma unroll
    for (int mt = 0; mt < 4; mt++)
#pragma unroll
        for (int nt = 0; nt < 2; nt++)
            wmma::load_matrix_sync(acc[mt][nt],
                g_bias_rep + n0 + wc * 32 + nt * 16, G4, wmma::mem_row_major);

    const int lrow  = t >> 1;
    const int lhalf = (t & 1) * 8;
    const float* gA = X + (size_t)(m0 + lrow) * I_ + lhalf;
    const float* gB = W + (size_t)(n0 + lrow) * I_ + lhalf;
    const int soff = lrow * LDS_T + lhalf;

    // prologue: stage chunk 0 into buffer 0, prefetch chunk 1
    float4 a0 = *(const float4*)(gA);
    float4 a1 = *(const float4*)(gA + 4);
    float4 b0 = *(const float4*)(gB);
    float4 b1 = *(const float4*)(gB + 4);
    half_store8(&sA[0][soff], a0, a1);
    half_store8(&sB[0][soff], b0, b1);
    a0 = *(const float4*)(gA + 16);
    a1 = *(const float4*)(gA + 20);
    b0 = *(const float4*)(gB + 16);
    b1 = *(const float4*)(gB + 20);
    __syncthreads();

    for (int it = 0; it < NIT; ++it) {
        const int cur = it & 1;

        if (it < NIT - 1) {
            half_store8(&sA[cur ^ 1][soff], a0, a1);
            half_store8(&sB[cur ^ 1][soff], b0, b1);
            if (it < NIT - 2) {
                const float* pa = gA + (it + 2) * 16;
                const float* pb = gB + (it + 2) * 16;
                a0 = *(const float4*)(pa);
                a1 = *(const float4*)(pa + 4);
                b0 = *(const float4*)(pb);
                b1 = *(const float4*)(pb + 4);
            }
        }

        wmma::fragment<wmma::matrix_a, 16, 16, 16, __half, wmma::row_major> af[4];
        wmma::fragment<wmma::matrix_b, 16, 16, 16, __half, wmma::col_major> bf[2];
#pragma unroll
        for (int mt = 0; mt < 4; mt++)
            wmma::load_matrix_sync(af[mt], &sA[cur][(wr * 64 + mt * 16) * LDS_T], LDS_T);
#pragma unroll
        for (int nt = 0; nt < 2; nt++)
            wmma::load_matrix_sync(bf[nt], &sB[cur][(wc * 32 + nt * 16) * LDS_T], LDS_T);
#pragma unroll
        for (int mt = 0; mt < 4; mt++)
#pragma unroll
            for (int nt = 0; nt < 2; nt++)
                wmma::mma_sync(acc[mt][nt], af[mt], bf[nt], acc[mt][nt]);
        __syncthreads();
    }

#pragma unroll
    for (int mt = 0; mt < 4; mt++)
#pragma unroll
        for (int nt = 0; nt < 2; nt++)
            wmma::store_matrix_sync(
                g_G + (size_t)(m0 + wr * 64 + mt * 16) * G4 + n0 + wc * 32 + nt * 16,
                acc[mt][nt], G4, wmma::mem_row_major);
}

// ---------------------------------------------------------------------------
// Phase 2: persistent LSTM recurrence on tensor cores (verified round 8).
// Keeps split-bf16 x3 (error feeds back through the recurrence).
// ---------------------------------------------------------------------------
#define LDW 520
#define LDH 520
#define LDC 36
#define OFF_WHI 0
#define OFF_WLO (OFF_WHI + 64 * LDW * 2)
#define OFF_HHI (OFF_WLO + 64 * LDW * 2)
#define OFF_HLO (OFF_HHI + 32 * LDH * 2)
#define OFF_GT  (OFF_HLO + 32 * LDH * 2)
#define LSTM_SMEM (OFF_GT + 64 * LDC * 4)

__global__ __launch_bounds__(256, 1) void lstm_wmma(const float* __restrict__ Whh)
{
    extern __shared__ char sm[];
    __nv_bfloat16* w_hi = (__nv_bfloat16*)(sm + OFF_WHI);
    __nv_bfloat16* w_lo = (__nv_bfloat16*)(sm + OFF_WLO);
    __nv_bfloat16* h_hi = (__nv_bfloat16*)(sm + OFF_HHI);
    __nv_bfloat16* h_lo = (__nv_bfloat16*)(sm + OFF_HLO);
    float*         gt   = (float*)(sm + OFF_GT);

    const int bid = blockIdx.x;
    const int cg  = bid >> 2;
    const int bg  = bid & 3;
    const int t   = threadIdx.x;
    const int wid = t >> 5;
    const int mt  = wid >> 1;
    const int nt  = wid & 1;

    {
        const int p   = t >> 2;
        const int ks  = (t & 3) * 128;
        const int j   = (p >> 4) * H_ + cg * 16 + (p & 15);
        const float* src = Whh + (size_t)j * H_ + ks;
        __nv_bfloat16* dh = w_hi + p * LDW + ks;
        __nv_bfloat16* dl = w_lo + p * LDW + ks;
#pragma unroll 8
        for (int i = 0; i < 128; i += 4) {
            float4 v = *(const float4*)(src + i);
            __nv_bfloat162 h0 = __floats2bfloat162_rn(v.x, v.y);
            __nv_bfloat162 h1 = __floats2bfloat162_rn(v.z, v.w);
            __nv_bfloat162 l0 = __floats2bfloat162_rn(v.x - __bfloat162float(h0.x),
                                                      v.y - __bfloat162float(h0.y));
            __nv_bfloat162 l1 = __floats2bfloat162_rn(v.z - __bfloat162float(h1.x),
                                                      v.w - __bfloat162float(h1.y));
            *(uint32_t*)(dh + i)     = *(uint32_t*)&h0;
            *(uint32_t*)(dh + i + 2) = *(uint32_t*)&h1;
            *(uint32_t*)(dl + i)     = *(uint32_t*)&l0;
            *(uint32_t*)(dl + i + 2) = *(uint32_t*)&l1;
        }
    }

    const int cc0 = 2 * t,     cc1 = 2 * t + 1;
    const int nn0 = cc0 >> 5,  bl0 = cc0 & 31;
    const int nn1 = cc1 >> 5,  bl1 = cc1 & 31;
    float creg0 = 0.0f, creg1 = 0.0f;
    const size_t gb0 = (size_t)(bg * 32 + bl0) * G4 + cg * 16 + nn0;
    const size_t gb1 = (size_t)(bg * 32 + bl1) * G4 + cg * 16 + nn1;

    __syncthreads();

    for (int s = 0; s < S_; ++s) {
        const float* Gs = g_G + (size_t)s * (B_ * G4);
        float pg0[4], pg1[4];
#pragma unroll
        for (int g = 0; g < 4; g++) {
            pg0[g] = Gs[gb0 + g * H_];
            pg1[g] = Gs[gb1 + g * H_];
        }

        {
            const float* h_in = g_h[s & 1];
            const int row = t >> 3;
            const int ks  = (t & 7) * 64;
            const float* src = h_in + (size_t)(bg * 32 + row) * H_ + ks;
            __nv_bfloat16* dh = h_hi + row * LDH + ks;
            __nv_bfloat16* dl = h_lo + row * LDH + ks;
#pragma unroll 4
            for (int i = 0; i < 64; i += 4) {
                float4 v = *(const float4*)(src + i);
                __nv_bfloat162 h0 = __floats2bfloat162_rn(v.x, v.y);
                __nv_bfloat162 h1 = __floats2bfloat162_rn(v.z, v.w);
                __nv_bfloat162 l0 = __floats2bfloat162_rn(v.x - __bfloat162float(h0.x),
                                                          v.y - __bfloat162float(h0.y));
                __nv_bfloat162 l1 = __floats2bfloat162_rn(v.z - __bfloat162float(h1.x),
                                                          v.w - __bfloat162float(h1.y));
                *(uint32_t*)(dh + i)     = *(uint32_t*)&h0;
                *(uint32_t*)(dh + i + 2) = *(uint32_t*)&h1;
                *(uint32_t*)(dl + i)     = *(uint32_t*)&l0;
                *(uint32_t*)(dl + i + 2) = *(uint32_t*)&l1;
            }
        }
        __syncthreads();

        {
            wmma::fragment<wmma::accumulator, 16, 16, 16, float> acc;
            wmma::fill_fragment(acc, 0.0f);
            const __nv_bfloat16* wbase_h = w_hi + (mt * 16) * LDW;
            const __nv_bfloat16* wbase_l = w_lo + (mt * 16) * LDW;
            const __nv_bfloat16* hbase_h = h_hi + (nt * 16) * LDH;
            const __nv_bfloat16* hbase_l = h_lo + (nt * 16) * LDH;
#pragma unroll 4
            for (int k = 0; k < 32; k++) {
                wmma::fragment<wmma::matrix_a, 16, 16, 16, __nv_bfloat16, wmma::row_major> a_h, a_l;
                wmma::fragment<wmma::matrix_b, 16, 16, 16, __nv_bfloat16, wmma::col_major> b_h, b_l;
                wmma::load_matrix_sync(a_h, wbase_h + k * 16, LDW);
                wmma::load_matrix_sync(a_l, wbase_l + k * 16, LDW);
                wmma::load_matrix_sync(b_h, hbase_h + k * 16, LDH);
                wmma::load_matrix_sync(b_l, hbase_l + k * 16, LDH);
                wmma::mma_sync(acc, a_h, b_h, acc);
                wmma::mma_sync(acc, a_h, b_l, acc);
                wmma::mma_sync(acc, a_l, b_h, acc);
            }
            wmma::store_matrix_sync(gt + (mt * 16) * LDC + nt * 16, acc, LDC,
                                    wmma::mem_row_major);
        }
        __syncthreads();

        float* h_out = g_h[(s + 1) & 1];
        {
            float gi = pg0[0] + gt[(0 * 16 + nn0) * LDC + bl0];
            float gf = pg0[1] + gt[(1 * 16 + nn0) * LDC + bl0];
            float gg = pg0[2] + gt[(2 * 16 + nn0) * LDC + bl0];
            float go = pg0[3] + gt[(3 * 16 + nn0) * LDC + bl0];
            float si = 1.0f / (1.0f + __expf(-gi));
            float sf = 1.0f / (1.0f + __expf(-gf));
            float tg = tanhf(gg);
            float so = 1.0f / (1.0f + __expf(-go));
            creg0 = sf * creg0 + si * tg;
            h_out[(size_t)(bg * 32 + bl0) * H_ + cg * 16 + nn0] = so * tanhf(creg0);
        }
        {
            float gi = pg1[0] + gt[(0 * 16 + nn1) * LDC + bl1];
            float gf = pg1[1] + gt[(1 * 16 + nn1) * LDC + bl1];
            float gg = pg1[2] + gt[(2 * 16 + nn1) * LDC + bl1];
            float go = pg1[3] + gt[(3 * 16 + nn1) * LDC + bl1];
            float si = 1.0f / (1.0f + __expf(-gi));
            float sf = 1.0f / (1.0f + __expf(-gf));
            float tg = tanhf(gg);
            float so = 1.0f / (1.0f + __expf(-go));
            creg1 = sf * creg1 + si * tg;
            h_out[(size_t)(bg * 32 + bl1) * H_ + cg * 16 + nn1] = so * tanhf(creg1);
        }

        __threadfence();
        __syncthreads();
        if (t == 0) {
            int old = atomicAdd(&g_cnt, 1);
            if (old == NBLK - 1) {
                atomicExch(&g_cnt, 0);
                __threadfence();
                g_gen = s + 1;
            } else {
                while (g_gen <= s) { }
                __threadfence();
            }
        }
        __syncthreads();
    }
}

// ---------------------------------------------------------------------------
// Final reduction
// ---------------------------------------------------------------------------
__global__ __launch_bounds__(1024) void reduce_h(float* __restrict__ out) {
    __shared__ float red[1024];
    const int t = threadIdx.x;
    float s = 0.0f;
    for (int i = t; i < B_ * H_; i += 1024) s += g_h[0][i];
    red[t] = s;
    __syncthreads();
    for (int off = 512; off > 0; off >>= 1) {
        if (t < off) red[t] += red[t + off];
        __syncthreads();
    }
    if (t == 0) out[0] = red[0];
}

// ---------------------------------------------------------------------------
// kernel_launch
// ---------------------------------------------------------------------------
extern "C" void kernel_launch(void* const* d_in, const int* in_sizes, int n_in,
                              void* d_out, int out_size) {
    const float* x    = (const float*)d_in[0];
    const float* w_ih = (const float*)d_in[1];
    const float* w_hh = (const float*)d_in[2];
    const float* b_ih = (const float*)d_in[3];
    const float* b_hh = (const float*)d_in[4];
    float* out = (float*)d_out;

    static_assert(LSTM_SMEM <= 227 * 1024, "smem overflow (lstm)");
    cudaFuncSetAttribute(lstm_wmma,
                         cudaFuncAttributeMaxDynamicSharedMemorySize,
                         LSTM_SMEM);

    init_state<<<(B_ * H_ + 255) / 256, 256>>>();
    fill_bias<<<(G4 + 255) / 256, 256>>>(b_ih, b_hh);

    dim3 ggrid(G4 / 128, M_TOT / 128);
    gemm_fp16<<<ggrid, 256>>>(x, w_ih);

    lstm_wmma<<<NBLK, 256, LSTM_SMEM>>>(w_hh);

    reduce_h<<<1, 1024>>>(out);
}